// round 2
// baseline (speedup 1.0000x reference)
#include <cuda_runtime.h>

// Problem constants (fixed by setup_inputs)
#define BATCH 1024
#define NPTS  128   // pred points
#define MPTS  128   // gt points
#define TIME  10
#define GPTS  (MPTS * TIME)   // 1280 interpolated gt points

// Scratch for deterministic two-stage reduction (no cudaMalloc allowed)
__device__ float g_part_pred2gt[BATCH];
__device__ float g_part_gt2pred[BATCH];
__device__ float g_part_mask[BATCH];

__global__ __launch_bounds__(128, 8)
void dmloss_stage1(const float* __restrict__ ini_pred,   // [B,N,2]
                   const float* __restrict__ pred_polys, // [B,N,2]
                   const float* __restrict__ gt_polys,   // [B,M,2]
                   const float* __restrict__ kmask)      // [B,M]
{
    __shared__ float2 s_interp[GPTS];   // 10 KB
    __shared__ float2 s_pred[NPTS];     // ini_pred points
    __shared__ float  r1[128], r2[128], r3[128];

    const int b   = blockIdx.x;
    const int tid = threadIdx.x;

    // ---- build interpolated gt polygon in smem ----
    const float2* gt = (const float2*)(gt_polys + (size_t)b * MPTS * 2);
    const float2  gcur  = gt[tid];
    const float2  gprev = gt[(tid + MPTS - 1) % MPTS];   // roll(shift=1)
    #pragma unroll
    for (int t = 0; t < TIME; t++) {
        const float st = (float)t / (float)TIME;
        const float rs = 1.0f - st;
        float2 v;
        v.x = gcur.x * st + gprev.x * rs;
        v.y = gcur.y * st + gprev.y * rs;
        s_interp[tid * TIME + t] = v;
    }

    const float2* ip = (const float2*)(ini_pred + (size_t)b * NPTS * 2);
    const float2  p  = ip[tid];
    s_pred[tid] = p;
    __syncthreads();

    // ---- pred -> nearest interpolated gt (argmin over 1280, first-index ties) ----
    float bestd = 3.402823466e38f;
    int   besti = 0;
    #pragma unroll 8
    for (int g = 0; g < GPTS; g++) {
        const float2 q  = s_interp[g];     // broadcast read, conflict-free
        const float  dx = p.x - q.x;
        const float  dy = p.y - q.y;
        const float  d  = dx * dx + dy * dy;
        if (d < bestd) { bestd = d; besti = g; }
    }
    const float2  ng = s_interp[besti];
    const float2* pp = (const float2*)(pred_polys + (size_t)b * NPTS * 2);
    const float2  pv = pp[tid];
    const float c1 = fabsf(pv.x - ng.x) + fabsf(pv.y - ng.y);   // L1 contribution

    // ---- gt -> nearest pred (argmin over 128) ----
    float bd2 = 3.402823466e38f;
    int   bi2 = 0;
    #pragma unroll 8
    for (int n = 0; n < NPTS; n++) {
        const float2 q  = s_pred[n];
        const float  dx = q.x - gcur.x;
        const float  dy = q.y - gcur.y;
        const float  d  = dx * dx + dy * dy;
        if (d < bd2) { bd2 = d; bi2 = n; }
    }
    const float2 nearp = pp[bi2];                // pred_polys_[b, argmin]
    const float  mk    = kmask[(size_t)b * MPTS + tid];
    const float c2 = (fabsf(nearp.x - gcur.x) + fabsf(nearp.y - gcur.y)) * mk;
    const float c3 = 2.0f * mk;                  // mask broadcast over 2 channels

    // ---- block tree reduction of the three sums ----
    r1[tid] = c1; r2[tid] = c2; r3[tid] = c3;
    __syncthreads();
    #pragma unroll
    for (int s = 64; s > 0; s >>= 1) {
        if (tid < s) {
            r1[tid] += r1[tid + s];
            r2[tid] += r2[tid + s];
            r3[tid] += r3[tid + s];
        }
        __syncthreads();
    }
    if (tid == 0) {
        g_part_pred2gt[b] = r1[0];
        g_part_gt2pred[b] = r2[0];
        g_part_mask[b]    = r3[0];
    }
}

__global__ __launch_bounds__(256)
void dmloss_stage2(float* __restrict__ out)
{
    __shared__ float s1[256], s2[256], s3[256];
    const int tid = threadIdx.x;
    float a = 0.0f, bsum = 0.0f, c = 0.0f;
    for (int i = tid; i < BATCH; i += 256) {
        a    += g_part_pred2gt[i];
        bsum += g_part_gt2pred[i];
        c    += g_part_mask[i];
    }
    s1[tid] = a; s2[tid] = bsum; s3[tid] = c;
    __syncthreads();
    #pragma unroll
    for (int s = 128; s > 0; s >>= 1) {
        if (tid < s) {
            s1[tid] += s1[tid + s];
            s2[tid] += s2[tid + s];
            s3[tid] += s3[tid + s];
        }
        __syncthreads();
    }
    if (tid == 0) {
        const float loss_pred2gt = s1[0] / (float)(BATCH * NPTS * 2);
        const float loss_gt2pred = s2[0] / (s3[0] + 1.0f);
        out[0] = (loss_gt2pred + loss_pred2gt) * 0.5f;
    }
}

extern "C" void kernel_launch(void* const* d_in, const int* in_sizes, int n_in,
                              void* d_out, int out_size)
{
    const float* ini_pred   = (const float*)d_in[0];
    const float* pred_polys = (const float*)d_in[1];
    const float* gt_polys   = (const float*)d_in[2];
    const float* kmask      = (const float*)d_in[3];
    float* out = (float*)d_out;

    dmloss_stage1<<<BATCH, 128>>>(ini_pred, pred_polys, gt_polys, kmask);
    dmloss_stage2<<<1, 256>>>(out);
}

// round 3
// speedup vs baseline: 2.4725x; 2.4725x over previous
#include <cuda_runtime.h>

#define BATCH 1024
#define NPTS  128
#define MPTS  128
#define TIME  10

// Scratch (no allocation allowed) + cross-block completion counter
__device__ float g_part1[BATCH];
__device__ float g_part2[BATCH];
__device__ float g_part3[BATCH];
__device__ unsigned int g_count = 0;

__global__ __launch_bounds__(128, 8)
void dmloss_fused(const float* __restrict__ ini_pred,   // [B,N,2]
                  const float* __restrict__ pred_polys, // [B,N,2]
                  const float* __restrict__ gt_polys,   // [B,M,2]
                  const float* __restrict__ kmask,      // [B,M]
                  float* __restrict__ out)
{
    __shared__ float4 s_seg[MPTS];    // ax, ay, ex, ey   (a = prev vertex, e = cur - prev)
    __shared__ float2 s_e2c[MPTS];    // e2, -10/e2
    __shared__ float2 s_gt[MPTS];     // current vertex b
    __shared__ float4 s_pp[NPTS];     // px, py, 0.5*(px^2+py^2), pad   (ini_pred)
    __shared__ float  s_step[TIME];   // exact k/10 in fp32
    __shared__ float  s_r1[128], s_r2[128], s_r3[128];
    __shared__ int    s_last;

    const int b   = blockIdx.x;
    const int tid = threadIdx.x;

    // ---- per-segment precompute ----
    const float2* gt = (const float2*)(gt_polys + (size_t)b * MPTS * 2);
    const float2 bcur  = gt[tid];
    const float2 aprev = gt[(tid + MPTS - 1) & (MPTS - 1)];   // roll(shift=1)
    {
        const float ex = bcur.x - aprev.x;
        const float ey = bcur.y - aprev.y;
        const float e2 = ex * ex + ey * ey;
        const float c  = -10.0f / fmaxf(e2, 1e-30f);
        s_seg[tid] = make_float4(aprev.x, aprev.y, ex, ey);
        s_e2c[tid] = make_float2(e2, c);
        s_gt[tid]  = bcur;
    }

    const float2* ip = (const float2*)(ini_pred + (size_t)b * NPTS * 2);
    const float2 p = ip[tid];
    s_pp[tid] = make_float4(p.x, p.y, 0.5f * (p.x * p.x + p.y * p.y), 0.0f);

    if (tid < TIME) s_step[tid] = (float)tid / 10.0f;   // IEEE-rounded, matches arange/10
    __syncthreads();

    // ---- pred -> nearest interpolated gt : analytic per-segment quadratic min ----
    float bestd = 3.402823466e38f;
    int   besti = 0;
    #pragma unroll 4
    for (int m = 0; m < MPTS; m++) {
        const float4 sg = s_seg[m];          // uniform index -> smem broadcast
        const float2 ec = s_e2c[m];
        const float wx = sg.x - p.x;
        const float wy = sg.y - p.y;
        const float wd = fmaf(wy, sg.w, wx * sg.z);          // w . e
        float kf = wd * ec.y;                                 // -10*(w.e)/e2 (vertex in k units)
        kf = fminf(fmaxf(kf, 0.0f), 9.0f);
        const int   k = __float2int_rn(kf);                   // integer minimizer of convex quad
        const float t = s_step[k];
        const float w2 = fmaf(wy, wy, wx * wx);
        const float d  = fmaf(t, fmaf(t, ec.x, wd + wd), w2); // w2 + 2t(w.e) + t^2 e2
        const int idx = m * TIME + k;
        if (d < bestd) { bestd = d; besti = idx; }
    }

    // nearest interp coordinates, computed with the reference's b*t + a*(1-t)
    float c1;
    {
        const int m = besti / TIME;
        const int k = besti - m * TIME;
        const float  t  = s_step[k];
        const float  rt = 1.0f - t;
        const float4 sg = s_seg[m];
        const float2 bb = s_gt[m];
        const float qx = bb.x * t + sg.x * rt;
        const float qy = bb.y * t + sg.y * rt;
        const float2* pp = (const float2*)(pred_polys + (size_t)b * NPTS * 2);
        const float2 pv = pp[tid];
        c1 = fabsf(pv.x - qx) + fabsf(pv.y - qy);
    }

    // ---- gt -> nearest pred : expanded score 0.5|q|^2 - g.q ----
    float bscore = 3.402823466e38f;
    int   bi2 = 0;
    #pragma unroll 4
    for (int n = 0; n < NPTS; n++) {
        const float4 q = s_pp[n];
        const float s = fmaf(-bcur.x, q.x, fmaf(-bcur.y, q.y, q.z));
        if (s < bscore) { bscore = s; bi2 = n; }
    }
    float c2, c3;
    {
        const float2* pp = (const float2*)(pred_polys + (size_t)b * NPTS * 2);
        const float2 nearp = pp[bi2];
        const float  mk = kmask[(size_t)b * MPTS + tid];
        c2 = (fabsf(nearp.x - bcur.x) + fabsf(nearp.y - bcur.y)) * mk;
        c3 = 2.0f * mk;
    }

    // ---- block tree reduction ----
    s_r1[tid] = c1; s_r2[tid] = c2; s_r3[tid] = c3;
    __syncthreads();
    #pragma unroll
    for (int s = 64; s > 0; s >>= 1) {
        if (tid < s) {
            s_r1[tid] += s_r1[tid + s];
            s_r2[tid] += s_r2[tid + s];
            s_r3[tid] += s_r3[tid + s];
        }
        __syncthreads();
    }
    if (tid == 0) {
        g_part1[b] = s_r1[0];
        g_part2[b] = s_r2[0];
        g_part3[b] = s_r3[0];
        __threadfence();
        const unsigned old = atomicAdd(&g_count, 1u);
        s_last = (old == (unsigned)(BATCH - 1)) ? 1 : 0;
    }
    __syncthreads();

    // ---- last block: deterministic final reduction ----
    if (s_last) {
        float a = 0.0f, bs = 0.0f, c = 0.0f;
        #pragma unroll
        for (int i = tid; i < BATCH; i += 128) {
            a  += g_part1[i];
            bs += g_part2[i];
            c  += g_part3[i];
        }
        s_r1[tid] = a; s_r2[tid] = bs; s_r3[tid] = c;
        __syncthreads();
        #pragma unroll
        for (int s = 64; s > 0; s >>= 1) {
            if (tid < s) {
                s_r1[tid] += s_r1[tid + s];
                s_r2[tid] += s_r2[tid + s];
                s_r3[tid] += s_r3[tid + s];
            }
            __syncthreads();
        }
        if (tid == 0) {
            const float loss_pred2gt = s_r1[0] / (float)(BATCH * NPTS * 2);
            const float loss_gt2pred = s_r2[0] / (s_r3[0] + 1.0f);
            out[0] = (loss_gt2pred + loss_pred2gt) * 0.5f;
            g_count = 0;   // reset for next graph replay
        }
    }
}

extern "C" void kernel_launch(void* const* d_in, const int* in_sizes, int n_in,
                              void* d_out, int out_size)
{
    const float* ini_pred   = (const float*)d_in[0];
    const float* pred_polys = (const float*)d_in[1];
    const float* gt_polys   = (const float*)d_in[2];
    const float* kmask      = (const float*)d_in[3];
    float* out = (float*)d_out;

    dmloss_fused<<<BATCH, 128>>>(ini_pred, pred_polys, gt_polys, kmask, out);
}